// round 3
// baseline (speedup 1.0000x reference)
#include <cuda_runtime.h>

#define CH_IN 32
#define CH_Y  16
#define WDIM  256
#define PLANE (256*256)
#define ROWS_PER_CTA 4

__global__ __launch_bounds__(256, 3)
void cross_modal_attn_kernel(
    const float* __restrict__ c,  const float* __restrict__ p,
    const float* __restrict__ Wq, const float* __restrict__ bq,
    const float* __restrict__ Wk, const float* __restrict__ bk,
    const float* __restrict__ Wv, const float* __restrict__ bv,
    const float* __restrict__ Wy, const float* __restrict__ by,
    float* __restrict__ out)
{
    const int tid  = threadIdx.x;      // = w, 0..255
    const int lane = tid & 31, warp = tid >> 5;
    const int b    = blockIdx.y;       // 0..15

    __shared__ float sWq[CH_Y*CH_IN], sWk[CH_Y*CH_IN], sWv[CH_Y*CH_IN];
    __shared__ float sWy[CH_IN*CH_Y];
    __shared__ float sbq[CH_Y], sbk[CH_Y], sbv[CH_Y], sby[CH_IN];
    __shared__ float sred[CH_Y][9];    // [channel][warp], padded
    __shared__ float sfin[CH_Y];

    // stage weights once per CTA (amortized over ROWS_PER_CTA rows)
    for (int i = tid; i < CH_Y*CH_IN; i += 256) {
        sWq[i] = Wq[i]; sWk[i] = Wk[i]; sWv[i] = Wv[i]; sWy[i] = Wy[i];
    }
    if (tid < CH_Y)  { sbq[tid] = bq[tid]; sbk[tid] = bk[tid]; sbv[tid] = bv[tid]; }
    if (tid < CH_IN) { sby[tid] = by[tid]; }
    __syncthreads();

    for (int r = 0; r < ROWS_PER_CTA; r++) {
        const int h = blockIdx.x * ROWS_PER_CTA + r;
        const size_t base_in  = ((size_t)b * CH_IN) * PLANE + (size_t)h * WDIM + tid;
        const size_t base_out = ((size_t)b * (2*CH_IN)) * PLANE + (size_t)h * WDIM + tid;

        // ---- streaming k,v accumulation over p channels ----
        float kk[CH_Y], vv[CH_Y];
#pragma unroll
        for (int cy = 0; cy < CH_Y; cy++) { kk[cy] = sbk[cy]; vv[cy] = sbv[cy]; }
#pragma unroll
        for (int ci = 0; ci < CH_IN; ci++) {
            const float x = __ldcs(p + base_in + (size_t)ci * PLANE);
#pragma unroll
            for (int cy = 0; cy < CH_Y; cy++) {
                kk[cy] = fmaf(sWk[cy*CH_IN + ci], x, kk[cy]);
                vv[cy] = fmaf(sWv[cy*CH_IN + ci], x, vv[cy]);
            }
        }

        // ---- streaming q accumulation over c channels + immediate concat copy ----
        float t[CH_Y];
#pragma unroll
        for (int cy = 0; cy < CH_Y; cy++) t[cy] = sbq[cy];
#pragma unroll
        for (int ci = 0; ci < CH_IN; ci++) {
            const float x = __ldcs(c + base_in + (size_t)ci * PLANE);
            __stcs(out + base_out + (size_t)(CH_IN + ci) * PLANE, x);
#pragma unroll
            for (int cy = 0; cy < CH_Y; cy++)
                t[cy] = fmaf(sWq[cy*CH_IN + ci], x, t[cy]);
        }

        // ---- softmax over w, no max-subtraction (|q*k| <~ 12, exp is fp32-safe) ----
#pragma unroll
        for (int cy = 0; cy < CH_Y; cy++) t[cy] = __expf(t[cy] * kk[cy]);

        // per-warp sum reduce, then cross-warp combine
#pragma unroll
        for (int cy = 0; cy < CH_Y; cy++) {
            float s = t[cy];
#pragma unroll
            for (int o = 16; o; o >>= 1) s += __shfl_xor_sync(0xffffffffu, s, o);
            if (lane == 0) sred[cy][warp] = s;
        }
        __syncthreads();
        if (tid < CH_Y) {
            float s = 0.0f;
#pragma unroll
            for (int wi = 0; wi < 8; wi++) s += sred[tid][wi];
            sfin[tid] = 1.0f / s;
        }
        __syncthreads();

#pragma unroll
        for (int cy = 0; cy < CH_Y; cy++) t[cy] = t[cy] * sfin[cy] * vv[cy];

        // ---- output conv 16->32 ----
#pragma unroll
        for (int co = 0; co < CH_IN; co++) {
            float a = sby[co];
#pragma unroll
            for (int cy = 0; cy < CH_Y; cy++)
                a = fmaf(sWy[co*CH_Y + cy], t[cy], a);
            __stcs(out + base_out + (size_t)co * PLANE, a);
        }
    }
}

extern "C" void kernel_launch(void* const* d_in, const int* in_sizes, int n_in,
                              void* d_out, int out_size)
{
    const float* c  = (const float*)d_in[0];
    const float* p  = (const float*)d_in[1];
    const float* Wq = (const float*)d_in[2];
    const float* bq = (const float*)d_in[3];
    const float* Wk = (const float*)d_in[4];
    const float* bk = (const float*)d_in[5];
    const float* Wv = (const float*)d_in[6];
    const float* bv = (const float*)d_in[7];
    const float* Wy = (const float*)d_in[8];
    const float* by = (const float*)d_in[9];
    float* out = (float*)d_out;

    dim3 grid(WDIM / ROWS_PER_CTA, 16);  // (H/4, B)
    dim3 block(256);                     // one thread per w
    cross_modal_attn_kernel<<<grid, block>>>(c, p, Wq, bq, Wk, bk, Wv, bv, Wy, by, out);
}

// round 4
// speedup vs baseline: 2.1271x; 2.1271x over previous
#include <cuda_runtime.h>

typedef unsigned long long u64;

#define CH_IN 32
#define CH_Y  16
#define WDIM  256
#define PLANE (256*256)
#define ROWS_PER_CTA 2

__device__ __forceinline__ u64 pack2(float lo, float hi) {
    u64 r; asm("mov.b64 %0, {%1, %2};" : "=l"(r) : "f"(lo), "f"(hi)); return r;
}
__device__ __forceinline__ void ffma2(u64& d, u64 a, u64 b) {
    asm("fma.rn.f32x2 %0, %1, %2, %0;" : "+l"(d) : "l"(a), "l"(b));
}
__device__ __forceinline__ float hsum_bias(u64 v, float b) {
    float lo, hi; asm("mov.b64 {%0, %1}, %2;" : "=f"(lo), "=f"(hi) : "l"(v));
    return b + lo + hi;
}
__device__ __forceinline__ u64 lds2(const float2* p) {
    float2 w = *p; return pack2(w.x, w.y);
}

__global__ __launch_bounds__(256, 2)
void cross_modal_attn_kernel(
    const float* __restrict__ c,  const float* __restrict__ p,
    const float* __restrict__ Wq, const float* __restrict__ bq,
    const float* __restrict__ Wk, const float* __restrict__ bk,
    const float* __restrict__ Wv, const float* __restrict__ bv,
    const float* __restrict__ Wy, const float* __restrict__ by,
    float* __restrict__ out)
{
    const int tid  = threadIdx.x;      // = w, 0..255
    const int lane = tid & 31, warp = tid >> 5;
    const int b    = blockIdx.y;       // 0..15

    // weight pairs stored as float2 (8B aligned) so reads are LDS.64
    __shared__ float2 sWq[CH_Y*CH_IN/2], sWk[CH_Y*CH_IN/2], sWv[CH_Y*CH_IN/2];
    __shared__ float2 sWy[CH_IN*CH_Y/2];
    __shared__ float sbq[CH_Y], sbk[CH_Y], sbv[CH_Y], sby[CH_IN];
    __shared__ float sred[CH_Y][9];
    __shared__ float sfin[CH_Y];

    {
        float* dWq = (float*)sWq; float* dWk = (float*)sWk;
        float* dWv = (float*)sWv; float* dWy = (float*)sWy;
        for (int i = tid; i < CH_Y*CH_IN; i += 256) {
            dWq[i] = Wq[i]; dWk[i] = Wk[i]; dWv[i] = Wv[i]; dWy[i] = Wy[i];
        }
    }
    if (tid < CH_Y)  { sbq[tid] = bq[tid]; sbk[tid] = bk[tid]; sbv[tid] = bv[tid]; }
    if (tid < CH_IN) { sby[tid] = by[tid]; }
    __syncthreads();

    for (int r = 0; r < ROWS_PER_CTA; r++) {
        const int h = blockIdx.x * ROWS_PER_CTA + r;
        const size_t base_in  = ((size_t)b * CH_IN) * PLANE + (size_t)h * WDIM + tid;
        const size_t base_out = ((size_t)b * (2*CH_IN)) * PLANE + (size_t)h * WDIM + tid;

        // ---- phase 1: batched load of p (MLP=32), pack over ci ----
        float px[CH_IN];
#pragma unroll
        for (int ci = 0; ci < CH_IN; ci++) px[ci] = __ldcs(p + base_in + (size_t)ci * PLANE);
        u64 xp[CH_IN/2];
#pragma unroll
        for (int j = 0; j < CH_IN/2; j++) xp[j] = pack2(px[2*j], px[2*j+1]);

        u64 ak[CH_Y], av[CH_Y];
#pragma unroll
        for (int cy = 0; cy < CH_Y; cy++) { ak[cy] = 0ULL; av[cy] = 0ULL; }
#pragma unroll
        for (int cy = 0; cy < CH_Y; cy++) {
#pragma unroll
            for (int j = 0; j < CH_IN/2; j++) {
                ffma2(ak[cy], lds2(&sWk[cy*(CH_IN/2) + j]), xp[j]);
                ffma2(av[cy], lds2(&sWv[cy*(CH_IN/2) + j]), xp[j]);
            }
        }
        float kk[CH_Y], vv[CH_Y];
#pragma unroll
        for (int cy = 0; cy < CH_Y; cy++) {
            kk[cy] = hsum_bias(ak[cy], sbk[cy]);
            vv[cy] = hsum_bias(av[cy], sbv[cy]);
        }

        // ---- phase 2: batched load of c, concat copy, q ----
        float cx[CH_IN];
#pragma unroll
        for (int ci = 0; ci < CH_IN; ci++) cx[ci] = __ldcs(c + base_in + (size_t)ci * PLANE);
#pragma unroll
        for (int ci = 0; ci < CH_IN; ci++)
            __stcs(out + base_out + (size_t)(CH_IN + ci) * PLANE, cx[ci]);
#pragma unroll
        for (int j = 0; j < CH_IN/2; j++) xp[j] = pack2(cx[2*j], cx[2*j+1]);

        u64 aq[CH_Y];
#pragma unroll
        for (int cy = 0; cy < CH_Y; cy++) aq[cy] = 0ULL;
#pragma unroll
        for (int cy = 0; cy < CH_Y; cy++) {
#pragma unroll
            for (int j = 0; j < CH_IN/2; j++)
                ffma2(aq[cy], lds2(&sWq[cy*(CH_IN/2) + j]), xp[j]);
        }

        // ---- softmax over w, no max-subtraction (|q*k| <~ 12, fp32-safe) ----
        float t[CH_Y];
#pragma unroll
        for (int cy = 0; cy < CH_Y; cy++)
            t[cy] = __expf(hsum_bias(aq[cy], sbq[cy]) * kk[cy]);

#pragma unroll
        for (int cy = 0; cy < CH_Y; cy++) {
            float s = t[cy];
#pragma unroll
            for (int o = 16; o; o >>= 1) s += __shfl_xor_sync(0xffffffffu, s, o);
            if (lane == 0) sred[cy][warp] = s;
        }
        __syncthreads();
        if (tid < CH_Y) {
            float s = 0.0f;
#pragma unroll
            for (int wi = 0; wi < 8; wi++) s += sred[tid][wi];
            sfin[tid] = 1.0f / s;
        }
        __syncthreads();

        u64 yp[CH_Y/2];
#pragma unroll
        for (int j = 0; j < CH_Y/2; j++) {
            float a = t[2*j]   * sfin[2*j]   * vv[2*j];
            float d = t[2*j+1] * sfin[2*j+1] * vv[2*j+1];
            yp[j] = pack2(a, d);
        }
        if (r + 1 < ROWS_PER_CTA) __syncthreads();  // protect sred reuse

        // ---- output conv 16->32, packed over cy ----
#pragma unroll
        for (int co = 0; co < CH_IN; co++) {
            u64 acc = 0ULL;
#pragma unroll
            for (int j = 0; j < CH_Y/2; j++)
                ffma2(acc, lds2(&sWy[co*(CH_Y/2) + j]), yp[j]);
            __stcs(out + base_out + (size_t)co * PLANE, hsum_bias(acc, sby[co]));
        }
    }
}

extern "C" void kernel_launch(void* const* d_in, const int* in_sizes, int n_in,
                              void* d_out, int out_size)
{
    const float* c  = (const float*)d_in[0];
    const float* p  = (const float*)d_in[1];
    const float* Wq = (const float*)d_in[2];
    const float* bq = (const float*)d_in[3];
    const float* Wk = (const float*)d_in[4];
    const float* bk = (const float*)d_in[5];
    const float* Wv = (const float*)d_in[6];
    const float* bv = (const float*)d_in[7];
    const float* Wy = (const float*)d_in[8];
    const float* by = (const float*)d_in[9];
    float* out = (float*)d_out;

    dim3 grid(WDIM / ROWS_PER_CTA, 16);  // (128, 16) = 2048 CTAs
    dim3 block(256);
    cross_modal_attn_kernel<<<grid, block>>>(c, p, Wq, bq, Wk, bk, Wv, bv, Wy, by, out);
}

// round 5
// speedup vs baseline: 2.2222x; 1.0447x over previous
#include <cuda_runtime.h>

typedef unsigned long long u64;

#define CH_IN 32
#define CH_Y  16
#define WDIM  256
#define PLANE (256*256)
#define ROWS_PER_CTA 2

__device__ __forceinline__ u64 pack2(float lo, float hi) {
    u64 r; asm("mov.b64 %0, {%1, %2};" : "=l"(r) : "f"(lo), "f"(hi)); return r;
}
__device__ __forceinline__ void ffma2(u64& d, u64 a, u64 b) {
    asm("fma.rn.f32x2 %0, %1, %2, %0;" : "+l"(d) : "l"(a), "l"(b));
}
__device__ __forceinline__ float hsum_bias(u64 v, float b) {
    float lo, hi; asm("mov.b64 {%0, %1}, %2;" : "=f"(lo), "=f"(hi) : "l"(v));
    return b + lo + hi;
}

__global__ __launch_bounds__(256, 2)
void cross_modal_attn_kernel(
    const float* __restrict__ c,  const float* __restrict__ p,
    const float* __restrict__ Wq, const float* __restrict__ bq,
    const float* __restrict__ Wk, const float* __restrict__ bk,
    const float* __restrict__ Wv, const float* __restrict__ bv,
    const float* __restrict__ Wy, const float* __restrict__ by,
    float* __restrict__ out)
{
    const int tid  = threadIdx.x;      // = w, 0..255
    const int lane = tid & 31, warp = tid >> 5;
    const int b    = blockIdx.y;       // 0..15

    // weights as float4 so each read is one LDS.128 feeding two FFMA2
    __shared__ float4 sWq[CH_Y*CH_IN/4], sWk[CH_Y*CH_IN/4], sWv[CH_Y*CH_IN/4];
    __shared__ float4 sWy[CH_IN*CH_Y/4];
    __shared__ float sbq[CH_Y], sbk[CH_Y], sbv[CH_Y], sby[CH_IN];
    __shared__ float sred[CH_Y][9];
    __shared__ float sfin[CH_Y];

    {
        float* dWq = (float*)sWq; float* dWk = (float*)sWk;
        float* dWv = (float*)sWv; float* dWy = (float*)sWy;
        for (int i = tid; i < CH_Y*CH_IN; i += 256) {
            dWq[i] = Wq[i]; dWk[i] = Wk[i]; dWv[i] = Wv[i]; dWy[i] = Wy[i];
        }
    }
    if (tid < CH_Y)  { sbq[tid] = bq[tid]; sbk[tid] = bk[tid]; sbv[tid] = bv[tid]; }
    if (tid < CH_IN) { sby[tid] = by[tid]; }
    __syncthreads();

    for (int r = 0; r < ROWS_PER_CTA; r++) {
        const int h = blockIdx.x * ROWS_PER_CTA + r;
        const size_t base_in  = ((size_t)b * CH_IN) * PLANE + (size_t)h * WDIM + tid;
        const size_t base_out = ((size_t)b * (2*CH_IN)) * PLANE + (size_t)h * WDIM + tid;

        // ---- phase 1: batched load of p (MLP=32), pack over ci ----
        float px[CH_IN];
#pragma unroll
        for (int ci = 0; ci < CH_IN; ci++) px[ci] = __ldcs(p + base_in + (size_t)ci * PLANE);
        u64 xp[CH_IN/2];
#pragma unroll
        for (int j = 0; j < CH_IN/2; j++) xp[j] = pack2(px[2*j], px[2*j+1]);

        u64 ak[CH_Y], av[CH_Y];
#pragma unroll
        for (int cy = 0; cy < CH_Y; cy++) { ak[cy] = 0ULL; av[cy] = 0ULL; }
#pragma unroll
        for (int cy = 0; cy < CH_Y; cy++) {
#pragma unroll
            for (int j4 = 0; j4 < CH_IN/4; j4++) {
                const float4 wk = sWk[cy*(CH_IN/4) + j4];
                ffma2(ak[cy], pack2(wk.x, wk.y), xp[2*j4]);
                ffma2(ak[cy], pack2(wk.z, wk.w), xp[2*j4+1]);
                const float4 wv = sWv[cy*(CH_IN/4) + j4];
                ffma2(av[cy], pack2(wv.x, wv.y), xp[2*j4]);
                ffma2(av[cy], pack2(wv.z, wv.w), xp[2*j4+1]);
            }
        }
        float kk[CH_Y], vv[CH_Y];
#pragma unroll
        for (int cy = 0; cy < CH_Y; cy++) {
            kk[cy] = hsum_bias(ak[cy], sbk[cy]);
            vv[cy] = hsum_bias(av[cy], sbv[cy]);
        }

        // ---- phase 2: batched load of c, concat copy, q ----
        float cx[CH_IN];
#pragma unroll
        for (int ci = 0; ci < CH_IN; ci++) cx[ci] = __ldcs(c + base_in + (size_t)ci * PLANE);
#pragma unroll
        for (int ci = 0; ci < CH_IN; ci++)
            __stcs(out + base_out + (size_t)(CH_IN + ci) * PLANE, cx[ci]);
#pragma unroll
        for (int j = 0; j < CH_IN/2; j++) xp[j] = pack2(cx[2*j], cx[2*j+1]);

        u64 aq[CH_Y];
#pragma unroll
        for (int cy = 0; cy < CH_Y; cy++) aq[cy] = 0ULL;
#pragma unroll
        for (int cy = 0; cy < CH_Y; cy++) {
#pragma unroll
            for (int j4 = 0; j4 < CH_IN/4; j4++) {
                const float4 wq = sWq[cy*(CH_IN/4) + j4];
                ffma2(aq[cy], pack2(wq.x, wq.y), xp[2*j4]);
                ffma2(aq[cy], pack2(wq.z, wq.w), xp[2*j4+1]);
            }
        }

        // ---- softmax over w, no max-subtraction (|q*k| <~ 12, fp32-safe) ----
        float t[CH_Y];
#pragma unroll
        for (int cy = 0; cy < CH_Y; cy++)
            t[cy] = __expf(hsum_bias(aq[cy], sbq[cy]) * kk[cy]);

#pragma unroll
        for (int cy = 0; cy < CH_Y; cy++) {
            float s = t[cy];
#pragma unroll
            for (int o = 16; o; o >>= 1) s += __shfl_xor_sync(0xffffffffu, s, o);
            if (lane == 0) sred[cy][warp] = s;
        }
        __syncthreads();
        if (tid < CH_Y) {
            float s = 0.0f;
#pragma unroll
            for (int wi = 0; wi < 8; wi++) s += sred[tid][wi];
            sfin[tid] = 1.0f / s;
        }
        __syncthreads();

        u64 yp[CH_Y/2];
#pragma unroll
        for (int j = 0; j < CH_Y/2; j++) {
            float a = t[2*j]   * sfin[2*j]   * vv[2*j];
            float d = t[2*j+1] * sfin[2*j+1] * vv[2*j+1];
            yp[j] = pack2(a, d);
        }
        if (r + 1 < ROWS_PER_CTA) __syncthreads();  // protect sred reuse

        // ---- output conv 16->32, one LDS.128 per 2 FFMA2 ----
#pragma unroll
        for (int co = 0; co < CH_IN; co++) {
            u64 acc = 0ULL;
#pragma unroll
            for (int j4 = 0; j4 < CH_Y/4; j4++) {
                const float4 wy = sWy[co*(CH_Y/4) + j4];
                ffma2(acc, pack2(wy.x, wy.y), yp[2*j4]);
                ffma2(acc, pack2(wy.z, wy.w), yp[2*j4+1]);
            }
            __stcs(out + base_out + (size_t)co * PLANE, hsum_bias(acc, sby[co]));
        }
    }
}

extern "C" void kernel_launch(void* const* d_in, const int* in_sizes, int n_in,
                              void* d_out, int out_size)
{
    const float* c  = (const float*)d_in[0];
    const float* p  = (const float*)d_in[1];
    const float* Wq = (const float*)d_in[2];
    const float* bq = (const float*)d_in[3];
    const float* Wk = (const float*)d_in[4];
    const float* bk = (const float*)d_in[5];
    const float* Wv = (const float*)d_in[6];
    const float* bv = (const float*)d_in[7];
    const float* Wy = (const float*)d_in[8];
    const float* by = (const float*)d_in[9];
    float* out = (float*)d_out;

    dim3 grid(WDIM / ROWS_PER_CTA, 16);  // (128, 16) = 2048 CTAs
    dim3 block(256);
    cross_modal_attn_kernel<<<grid, block>>>(c, p, Wq, bq, Wk, bk, Wv, bv, Wy, by, out);
}

// round 6
// speedup vs baseline: 2.9153x; 1.3119x over previous
#include <cuda_runtime.h>

typedef unsigned long long u64;

#define CH_IN 32
#define CH_Y  16
#define WDIM  256
#define PLANE (256*256)
#define ROWS_PER_CTA 2
#define NTHR 128            // one row: thread t owns w = 2t, 2t+1

__device__ __forceinline__ u64 pack2(float lo, float hi) {
    u64 r; asm("mov.b64 %0, {%1, %2};" : "=l"(r) : "f"(lo), "f"(hi)); return r;
}
__device__ __forceinline__ u64 dup2(float w) {
    u64 r; asm("mov.b64 %0, {%1, %1};" : "=l"(r) : "f"(w)); return r;
}
__device__ __forceinline__ void ffma2(u64& d, u64 a, u64 b) {
    asm("fma.rn.f32x2 %0, %1, %2, %0;" : "+l"(d) : "l"(a), "l"(b));
}
__device__ __forceinline__ u64 mul2(u64 a, u64 b) {
    u64 r; asm("mul.rn.f32x2 %0, %1, %2;" : "=l"(r) : "l"(a), "l"(b)); return r;
}
__device__ __forceinline__ float lo2(u64 v) {
    float lo, hi; asm("mov.b64 {%0, %1}, %2;" : "=f"(lo), "=f"(hi) : "l"(v)); return lo;
}
__device__ __forceinline__ float hi2(u64 v) {
    float lo, hi; asm("mov.b64 {%0, %1}, %2;" : "=f"(lo), "=f"(hi) : "l"(v)); return hi;
}

__global__ __launch_bounds__(NTHR, 3)
void cross_modal_attn_kernel(
    const float* __restrict__ c,  const float* __restrict__ p,
    const float* __restrict__ Wq, const float* __restrict__ bq,
    const float* __restrict__ Wk, const float* __restrict__ bk,
    const float* __restrict__ Wv, const float* __restrict__ bv,
    const float* __restrict__ Wy, const float* __restrict__ by,
    float* __restrict__ out)
{
    const int tid  = threadIdx.x;      // 0..127; pixels w=2tid, 2tid+1
    const int lane = tid & 31, warp = tid >> 5;
    const int b    = blockIdx.y;

    __shared__ float4 sWq[CH_Y*CH_IN/4], sWk[CH_Y*CH_IN/4], sWv[CH_Y*CH_IN/4];
    __shared__ float4 sWy[CH_IN*CH_Y/4];
    __shared__ float sbq[CH_Y], sbk[CH_Y], sbv[CH_Y], sby[CH_IN];
    __shared__ float sred[CH_Y][5];    // [channel][warp], 4 warps + pad
    __shared__ float sfin[CH_Y];

    {
        float* dWq = (float*)sWq; float* dWk = (float*)sWk;
        float* dWv = (float*)sWv; float* dWy = (float*)sWy;
        for (int i = tid; i < CH_Y*CH_IN; i += NTHR) {
            dWq[i] = Wq[i]; dWk[i] = Wk[i]; dWv[i] = Wv[i]; dWy[i] = Wy[i];
        }
    }
    if (tid < CH_Y)  { sbq[tid] = bq[tid]; sbk[tid] = bk[tid]; sbv[tid] = bv[tid]; }
    if (tid < CH_IN) { sby[tid] = by[tid]; }
    __syncthreads();

    for (int r = 0; r < ROWS_PER_CTA; r++) {
        const int h = blockIdx.x * ROWS_PER_CTA + r;
        // float2 element index (w pair)
        const size_t base_in2  = (((size_t)b * CH_IN) * PLANE + (size_t)h * WDIM) / 2 + tid;
        const size_t base_out2 = (((size_t)b * (2*CH_IN)) * PLANE + (size_t)h * WDIM) / 2 + tid;
        const float2* p2 = (const float2*)p;
        const float2* c2 = (const float2*)c;
        float2* o2 = (float2*)out;

        // ---- phase 1: p -> k,v (pixel-pair packed), 2 chunks of 16 ci ----
        u64 kk[CH_Y], vv[CH_Y];
#pragma unroll
        for (int cy = 0; cy < CH_Y; cy++) { kk[cy] = dup2(sbk[cy]); vv[cy] = dup2(sbv[cy]); }

#pragma unroll
        for (int ch = 0; ch < 2; ch++) {
            u64 xp[16];
#pragma unroll
            for (int j = 0; j < 16; j++) {
                float2 v2 = __ldcs(p2 + base_in2 + (size_t)(ch*16 + j) * (PLANE/2));
                xp[j] = pack2(v2.x, v2.y);
            }
#pragma unroll
            for (int cy = 0; cy < CH_Y; cy++) {
#pragma unroll
                for (int j4 = 0; j4 < 4; j4++) {
                    const float4 wk = sWk[cy*(CH_IN/4) + ch*4 + j4];
                    ffma2(kk[cy], dup2(wk.x), xp[4*j4+0]);
                    ffma2(kk[cy], dup2(wk.y), xp[4*j4+1]);
                    ffma2(kk[cy], dup2(wk.z), xp[4*j4+2]);
                    ffma2(kk[cy], dup2(wk.w), xp[4*j4+3]);
                    const float4 wv = sWv[cy*(CH_IN/4) + ch*4 + j4];
                    ffma2(vv[cy], dup2(wv.x), xp[4*j4+0]);
                    ffma2(vv[cy], dup2(wv.y), xp[4*j4+1]);
                    ffma2(vv[cy], dup2(wv.z), xp[4*j4+2]);
                    ffma2(vv[cy], dup2(wv.w), xp[4*j4+3]);
                }
            }
        }

        // ---- phase 2: c -> q (packed) + concat copy ----
        u64 aq[CH_Y];
#pragma unroll
        for (int cy = 0; cy < CH_Y; cy++) aq[cy] = dup2(sbq[cy]);

#pragma unroll
        for (int ch = 0; ch < 2; ch++) {
            u64 xp[16];
#pragma unroll
            for (int j = 0; j < 16; j++) {
                float2 v2 = __ldcs(c2 + base_in2 + (size_t)(ch*16 + j) * (PLANE/2));
                xp[j] = pack2(v2.x, v2.y);
            }
#pragma unroll
            for (int j = 0; j < 16; j++) {
                float2 w2; w2.x = lo2(xp[j]); w2.y = hi2(xp[j]);
                __stcs(o2 + base_out2 + (size_t)(CH_IN + ch*16 + j) * (PLANE/2), w2);
            }
#pragma unroll
            for (int cy = 0; cy < CH_Y; cy++) {
#pragma unroll
                for (int j4 = 0; j4 < 4; j4++) {
                    const float4 wq = sWq[cy*(CH_IN/4) + ch*4 + j4];
                    ffma2(aq[cy], dup2(wq.x), xp[4*j4+0]);
                    ffma2(aq[cy], dup2(wq.y), xp[4*j4+1]);
                    ffma2(aq[cy], dup2(wq.z), xp[4*j4+2]);
                    ffma2(aq[cy], dup2(wq.w), xp[4*j4+3]);
                }
            }
        }

        // ---- t = exp(q*k), packed halves; no max-subtraction (|q*k|<~12) ----
#pragma unroll
        for (int cy = 0; cy < CH_Y; cy++) {
            u64 qk = mul2(aq[cy], kk[cy]);
            aq[cy] = pack2(__expf(lo2(qk)), __expf(hi2(qk)));
        }

        // ---- row sum over 256 pixels: pair-halves + 128 threads (4 warps) ----
#pragma unroll
        for (int cy = 0; cy < CH_Y; cy++) {
            float s = lo2(aq[cy]) + hi2(aq[cy]);
#pragma unroll
            for (int o = 16; o; o >>= 1) s += __shfl_xor_sync(0xffffffffu, s, o);
            if (lane == 0) sred[cy][warp] = s;
        }
        __syncthreads();
        if (tid < CH_Y) {
            float s = sred[tid][0] + sred[tid][1] + sred[tid][2] + sred[tid][3];
            sfin[tid] = 1.0f / s;
        }
        __syncthreads();

        // y = t * rinv * v   (packed)
        u64 yp[CH_Y];
#pragma unroll
        for (int cy = 0; cy < CH_Y; cy++)
            yp[cy] = mul2(mul2(aq[cy], dup2(sfin[cy])), vv[cy]);
        if (r + 1 < ROWS_PER_CTA) __syncthreads();  // protect sred reuse

        // ---- output conv 16->32, packed over pixel pair ----
#pragma unroll
        for (int co = 0; co < CH_IN; co++) {
            u64 acc = dup2(sby[co]);
#pragma unroll
            for (int j4 = 0; j4 < CH_Y/4; j4++) {
                const float4 wy = sWy[co*(CH_Y/4) + j4];
                ffma2(acc, dup2(wy.x), yp[4*j4+0]);
                ffma2(acc, dup2(wy.y), yp[4*j4+1]);
                ffma2(acc, dup2(wy.z), yp[4*j4+2]);
                ffma2(acc, dup2(wy.w), yp[4*j4+3]);
            }
            float2 w2; w2.x = lo2(acc); w2.y = hi2(acc);
            __stcs(o2 + base_out2 + (size_t)co * (PLANE/2), w2);
        }
    }
}

extern "C" void kernel_launch(void* const* d_in, const int* in_sizes, int n_in,
                              void* d_out, int out_size)
{
    const float* c  = (const float*)d_in[0];
    const float* p  = (const float*)d_in[1];
    const float* Wq = (const float*)d_in[2];
    const float* bq = (const float*)d_in[3];
    const float* Wk = (const float*)d_in[4];
    const float* bk = (const float*)d_in[5];
    const float* Wv = (const float*)d_in[6];
    const float* bv = (const float*)d_in[7];
    const float* Wy = (const float*)d_in[8];
    const float* by = (const float*)d_in[9];
    float* out = (float*)d_out;

    dim3 grid(WDIM / ROWS_PER_CTA, 16);  // (128, 16) = 2048 CTAs
    dim3 block(NTHR);                    // 128 threads = one row of pixel pairs
    cross_modal_attn_kernel<<<grid, block>>>(c, p, Wq, bq, Wk, bk, Wv, bv, Wy, by, out);
}